// round 15
// baseline (speedup 1.0000x reference)
#include <cuda_runtime.h>
#include <cuda_bf16.h>

#define THREADS 256
#define T_STEPS 20
#define BETA 0.9f
#define THR 1.0f

typedef unsigned int u32;
typedef unsigned long long u64;

// ---- weight fragments in device globals (filled by prep kernel) ----
__device__ u64 gW2f[3 * 16 * 8 * 32];   // [s][nb16][kc8][lane]
__device__ u64 gW3f[3 * 8 * 8 * 32];    // [s][nb8][kc8][lane]
__device__ u64 gW1f[3 * 16 * 32];       // [s][nb16][lane]
__device__ u64 gW4f[3 * 2 * 4 * 32];    // [s][nb2][kc4][lane]

// ---- smem byte offsets (spike/x buffers only) ----
#define SS1 0        // 32 x 256B
#define SS2 8192     // 32 x 256B
#define SS3 16384    // 32 x 128B
#define SXS 20480    // 3 x 32 x 32B
#define SM_TOTAL 23552

__device__ __forceinline__ float bfv(float v) { return __bfloat162float(__float2bfloat16(v)); }
__device__ __forceinline__ u32 bfb(float v) { return (u32)__bfloat16_as_ushort(__float2bfloat16(v)); }

__device__ __forceinline__ float split_lvl(float v, int s) {
    float s0 = bfv(v);
    if (s == 0) return s0;
    float r = v - s0;
    float s1 = bfv(r);
    if (s == 1) return s1;
    return bfv(r - s1);
}

__global__ void prep_kernel(const float* __restrict__ w1g, const float* __restrict__ w2g,
                            const float* __restrict__ w3g, const float* __restrict__ w4g)
{
    int idx = blockIdx.x * blockDim.x + threadIdx.x;
    int lane = idx & 31;
    int nrow = lane >> 2;
    int koff = (lane & 3) * 2;
    if (idx < 12288) {             // W2: [3][16][8][32]
        int f = idx >> 5; int kc = f & 7; int nb = (f >> 3) & 15; int s = f >> 7;
        int n = nb * 8 + nrow; int k = kc * 16 + koff;
        u32 lo = bfb(split_lvl(w2g[n * 128 + k], s))     | (bfb(split_lvl(w2g[n * 128 + k + 1], s)) << 16);
        u32 hi = bfb(split_lvl(w2g[n * 128 + k + 8], s)) | (bfb(split_lvl(w2g[n * 128 + k + 9], s)) << 16);
        gW2f[idx] = (u64)lo | ((u64)hi << 32);
    } else if (idx < 18432) {      // W3: [3][8][8][32]
        int j = idx - 12288; int f = j >> 5; int kc = f & 7; int nb = (f >> 3) & 7; int s = f >> 6;
        int n = nb * 8 + nrow; int k = kc * 16 + koff;
        u32 lo = bfb(split_lvl(w3g[n * 128 + k], s))     | (bfb(split_lvl(w3g[n * 128 + k + 1], s)) << 16);
        u32 hi = bfb(split_lvl(w3g[n * 128 + k + 8], s)) | (bfb(split_lvl(w3g[n * 128 + k + 9], s)) << 16);
        gW3f[j] = (u64)lo | ((u64)hi << 32);
    } else if (idx < 19968) {      // W1: [3][16][32]
        int j = idx - 18432; int f = j >> 5; int nb = f & 15; int s = f >> 4;
        int n = nb * 8 + nrow; int k = koff;
        u32 lo = bfb(split_lvl(w1g[n * 16 + k], s))     | (bfb(split_lvl(w1g[n * 16 + k + 1], s)) << 16);
        u32 hi = bfb(split_lvl(w1g[n * 16 + k + 8], s)) | (bfb(split_lvl(w1g[n * 16 + k + 9], s)) << 16);
        gW1f[j] = (u64)lo | ((u64)hi << 32);
    } else if (idx < 20736) {      // W4: [3][2][4][32]
        int j = idx - 19968; int f = j >> 5; int kc = f & 3; int nb = (f >> 2) & 1; int s = f >> 3;
        int n = nb * 8 + nrow; int k = kc * 16 + koff;
        float a0 = (n < 10) ? w4g[n * 64 + k]     : 0.f;
        float a1 = (n < 10) ? w4g[n * 64 + k + 1] : 0.f;
        float a2 = (n < 10) ? w4g[n * 64 + k + 8] : 0.f;
        float a3 = (n < 10) ? w4g[n * 64 + k + 9] : 0.f;
        u32 lo = bfb(split_lvl(a0, s)) | (bfb(split_lvl(a1, s)) << 16);
        u32 hi = bfb(split_lvl(a2, s)) | (bfb(split_lvl(a3, s)) << 16);
        gW4f[j] = (u64)lo | ((u64)hi << 32);
    }
}

__device__ __forceinline__ void ldsm4(u32 a[4], u32 addr) {
    asm volatile("ldmatrix.sync.aligned.m8n8.x4.shared.b16 {%0,%1,%2,%3}, [%4];"
        : "=r"(a[0]), "=r"(a[1]), "=r"(a[2]), "=r"(a[3]) : "r"(addr));
}
__device__ __forceinline__ void mma_bf16(float d[4], const u32 a[4], u32 b0, u32 b1) {
    asm volatile("mma.sync.aligned.m16n8k16.row.col.f32.bf16.bf16.f32 "
        "{%0,%1,%2,%3}, {%4,%5,%6,%7}, {%8,%9}, {%0,%1,%2,%3};"
        : "+f"(d[0]), "+f"(d[1]), "+f"(d[2]), "+f"(d[3])
        : "r"(a[0]), "r"(a[1]), "r"(a[2]), "r"(a[3]), "r"(b0), "r"(b1));
}
__device__ __forceinline__ void sts32(u32 addr, u32 v) {
    asm volatile("st.shared.b32 [%0], %1;" :: "r"(addr), "r"(v) : "memory");
}

__device__ __forceinline__ void lif4(float* mem, const float* d, u32 &p0, u32 &p1) {
    float s[4];
#pragma unroll
    for (int e = 0; e < 4; e++) {
        float m = mem[e];
        float reset = (m > THR) ? 1.0f : 0.0f;
        m = fmaf(BETA, m, d[e]) - reset;
        mem[e] = m;
        s[e] = (m > THR) ? 1.0f : 0.0f;
    }
    p0 = (s[0] != 0.0f ? 0x3F80u : 0u) | (s[1] != 0.0f ? 0x3F800000u : 0u);
    p1 = (s[2] != 0.0f ? 0x3F80u : 0u) | (s[3] != 0.0f ? 0x3F800000u : 0u);
}

__global__ void __launch_bounds__(THREADS, 2)
snn_mma_kernel(const float* __restrict__ x,
               float* __restrict__ out,
               int Btot)
{
    __shared__ __align__(16) char sm[SM_TOTAL];
    u32 smb;
    asm("{ .reg .u64 t; cvta.to.shared.u64 t, %1; cvt.u32.u64 %0, t; }"
        : "=r"(smb) : "l"(sm));

    const int tid  = threadIdx.x;
    const int w    = tid >> 5;     // 8 warps
    const int lane = tid & 31;
    const int b0   = blockIdx.x * 32;

    // ---- lane roles ----
    const int arow = ((lane >> 3) & 1) * 8 + (lane & 7);
    const int ac   = lane >> 4;
    const int r_   = lane >> 2;
    const int c_   = lane & 3;
    const u32 rx8  = (u32)(lane & 7) << 4;

    // ---- warp roles ----
    // L1/L2: Mh = w>>2 (m16 block), Nq = w&3 (n32 group -> n8 blocks 4Nq..4Nq+3)
    // L3:    Mh,  Nq -> n16 group (n8 blocks 2Nq, 2Nq+1)
    // L4:    warps 0..3: Mw4 = w>>1, nb4 = w&1
    const int Mh  = w >> 2;
    const int Nq  = w & 3;
    const int Mw4 = w >> 1, nb4 = w & 1;

    const u64* pW2 = gW2f + lane;
    const u64* pW3 = gW3f + lane;
    const u64* pW4 = gW4f + lane;

    // ---- hoist L1 B fragments (constant over t): 3 lv x 4 n8-blocks ----
    u32 bw1[3][4][2];
#pragma unroll
    for (int lv = 0; lv < 3; lv++)
#pragma unroll
        for (int j = 0; j < 4; j++) {
            u64 q = gW1f[(lv * 16 + (Nq * 4 + j)) * 32 + lane];
            bw1[lv][j][0] = (u32)q;
            bw1[lv][j][1] = (u32)(q >> 32);
        }

    // ---- membranes (registers) ----
    float m1[16], m2[16], m3[8], m4[4];
#pragma unroll
    for (int i = 0; i < 16; i++) { m1[i] = 0.f; m2[i] = 0.f; }
#pragma unroll
    for (int i = 0; i < 8; i++)  m3[i] = 0.f;
#pragma unroll
    for (int i = 0; i < 4; i++)  m4[i] = 0.f;

    // ---- x staging role: thread owns (batch bsx, feats fx, fx+1) ----
    const int bsx = tid >> 3;
    const int fx  = (tid & 7) * 2;
    const u32 xbase = smb + SXS + (u32)(bsx * 32 + (((fx >> 3) ^ (bsx & 1)) << 4) + (fx & 7) * 2);

    auto stage_x = [&](const float2& v) {
        float e0 = v.x - bfv(v.x), e1 = v.y - bfv(v.y);
        float g0 = e0 - bfv(e0),  g1 = e1 - bfv(e1);
        sts32(xbase,        bfb(v.x) | (bfb(v.y) << 16));
        sts32(xbase + 1024, bfb(e0) | (bfb(e1) << 16));
        sts32(xbase + 2048, bfb(g0) | (bfb(g1) << 16));
    };

    auto do_L1 = [&]() {   // warp M16 x N32, K=16, 6 split terms -> s1
        float acc[16];
#pragma unroll
        for (int i = 0; i < 16; i++) acc[i] = 0.f;
        const int la[6] = {0, 0, 1, 0, 1, 2};
        const int lb[6] = {0, 1, 0, 2, 1, 0};
        u32 ax[3][4];
#pragma unroll
        for (int lv = 0; lv < 3; lv++)
            ldsm4(ax[lv], smb + SXS + (u32)(lv * 1024 + (16 * Mh + arow) * 32)
                          + (((u32)ac << 4) ^ ((u32)(arow & 1) << 4)));
#pragma unroll
        for (int s = 0; s < 6; s++)
#pragma unroll
            for (int j = 0; j < 4; j++)
                mma_bf16(&acc[j * 4], ax[la[s]], bw1[lb[s]][j][0], bw1[lb[s]][j][1]);
#pragma unroll
        for (int j = 0; j < 4; j++) {
            u32 p0, p1;
            lif4(&m1[j * 4], &acc[j * 4], p0, p1);
            u32 a0 = smb + SS1 + (u32)((16 * Mh + r_) * 256)
                     + (((u32)(4 * Nq + j) << 4) ^ ((u32)r_ << 4)) + 4 * c_;
            sts32(a0, p0);
            sts32(a0 + 2048, p1);
        }
    };

    auto do_L4 = [&](int tt) {   // warps 0..3: M16 x N8, K=64
        float acc[4] = {0.f, 0.f, 0.f, 0.f};
#pragma unroll
        for (int kc = 0; kc < 4; kc++) {
            u32 a_[4];
            ldsm4(a_, smb + SS3 + (u32)((16 * Mw4 + arow) * 128)
                      + (((u32)(2 * kc + ac) << 4) ^ rx8));
#pragma unroll
            for (int s = 0; s < 3; s++) {
                u64 q = pW4[((s * 2 + nb4) * 4 + kc) * 32];
                mma_bf16(acc, a_, (u32)q, (u32)(q >> 32));
            }
        }
        float s4[4];
#pragma unroll
        for (int e = 0; e < 4; e++) {
            float m = m4[e];
            float reset = (m > THR) ? 1.0f : 0.0f;
            m = fmaf(BETA, m, acc[e]) - reset;
            m4[e] = m;
            s4[e] = (m > THR) ? 1.0f : 0.0f;
        }
        size_t row0 = (size_t)tt * (size_t)Btot + (size_t)(b0 + 16 * Mw4 + r_);
        if (nb4 == 0) {
            *(float2*)(out + row0 * 10 + 2 * c_)       = make_float2(s4[0], s4[1]);
            *(float2*)(out + (row0 + 8) * 10 + 2 * c_) = make_float2(s4[2], s4[3]);
        } else if (c_ == 0) {
            *(float2*)(out + row0 * 10 + 8)       = make_float2(s4[0], s4[1]);
            *(float2*)(out + (row0 + 8) * 10 + 8) = make_float2(s4[2], s4[3]);
        }
    };

    // ===== prologue: stage x(0); L1(0) =====
    {
        float2 v = *(const float2*)(x + ((size_t)0 * (size_t)Btot + (size_t)(b0 + bsx)) * 16 + fx);
        stage_x(v);
    }
    __syncthreads();
    do_L1();
    __syncthreads();

    for (int t = 0; t < T_STEPS; t++) {
        // ===== phase A: L4(t-1) [warps 0..3] + L2(t) + stage x(t+1) =====
        {
            float2 xv = make_float2(0.f, 0.f);
            if (t + 1 < T_STEPS)
                xv = *(const float2*)(x + ((size_t)(t + 1) * (size_t)Btot + (size_t)(b0 + bsx)) * 16 + fx);

            if (t > 0 && w < 4)
                do_L4(t - 1);

            // L2: warp M16 x N32, K=128, 3 splits
            float acc[16];
#pragma unroll
            for (int i = 0; i < 16; i++) acc[i] = 0.f;
#pragma unroll
            for (int kc = 0; kc < 8; kc++) {
                u32 a_[4];
                ldsm4(a_, smb + SS1 + (u32)((16 * Mh + arow) * 256)
                          + (((u32)(2 * kc + ac) << 4) ^ rx8));
#pragma unroll
                for (int s = 0; s < 3; s++) {
                    u64 q[4];
#pragma unroll
                    for (int j = 0; j < 4; j++)
                        q[j] = pW2[((s * 16 + (Nq * 4 + j)) * 8 + kc) * 32];
#pragma unroll
                    for (int j = 0; j < 4; j++)
                        mma_bf16(&acc[j * 4], a_, (u32)q[j], (u32)(q[j] >> 32));
                }
            }
#pragma unroll
            for (int j = 0; j < 4; j++) {
                u32 p0, p1;
                lif4(&m2[j * 4], &acc[j * 4], p0, p1);
                u32 a0 = smb + SS2 + (u32)((16 * Mh + r_) * 256)
                         + (((u32)(4 * Nq + j) << 4) ^ ((u32)r_ << 4)) + 4 * c_;
                sts32(a0, p0);
                sts32(a0 + 2048, p1);
            }

            if (t + 1 < T_STEPS)
                stage_x(xv);
        }
        __syncthreads();

        // ===== phase B: L3(t) + L1(t+1) =====
        {
            // L3: warp M16 x N16 (n8 blocks 2Nq, 2Nq+1), K=128, 3 splits
            float acc[8];
#pragma unroll
            for (int i = 0; i < 8; i++) acc[i] = 0.f;
#pragma unroll
            for (int kc = 0; kc < 8; kc++) {
                u32 a_[4];
                ldsm4(a_, smb + SS2 + (u32)((16 * Mh + arow) * 256)
                          + (((u32)(2 * kc + ac) << 4) ^ rx8));
#pragma unroll
                for (int s = 0; s < 3; s++) {
                    u64 q0 = pW3[((s * 8 + (2 * Nq + 0)) * 8 + kc) * 32];
                    u64 q1 = pW3[((s * 8 + (2 * Nq + 1)) * 8 + kc) * 32];
                    mma_bf16(&acc[0], a_, (u32)q0, (u32)(q0 >> 32));
                    mma_bf16(&acc[4], a_, (u32)q1, (u32)(q1 >> 32));
                }
            }
#pragma unroll
            for (int nb = 0; nb < 2; nb++) {
                u32 p0, p1;
                lif4(&m3[nb * 4], &acc[nb * 4], p0, p1);
                u32 a0 = smb + SS3 + (u32)((16 * Mh + r_) * 128)
                         + (((u32)(2 * Nq + nb) << 4) ^ ((u32)r_ << 4)) + 4 * c_;
                sts32(a0, p0);
                sts32(a0 + 1024, p1);
            }

            if (t + 1 < T_STEPS)
                do_L1();
        }
        __syncthreads();
    }

    // ===== epilogue: L4(T-1) =====
    if (w < 4)
        do_L4(T_STEPS - 1);
}

extern "C" void kernel_launch(void* const* d_in, const int* in_sizes, int n_in,
                              void* d_out, int out_size) {
    const float* x  = (const float*)d_in[0];
    const float* w1 = (const float*)d_in[1];
    const float* w2 = (const float*)d_in[2];
    const float* w3 = (const float*)d_in[3];
    const float* w4 = (const float*)d_in[4];
    float* out = (float*)d_out;

    const int Btot = in_sizes[0] / (T_STEPS * 16);  // 65536

    prep_kernel<<<(20736 + 127) / 128, 128>>>(w1, w2, w3, w4);

    const int grid = Btot / 32;                     // 2048
    snn_mma_kernel<<<grid, THREADS>>>(x, out, Btot);
}

// round 16
// speedup vs baseline: 1.0766x; 1.0766x over previous
#include <cuda_runtime.h>
#include <cuda_bf16.h>

#define THREADS 128
#define T_STEPS 20
#define BETA 0.9f
#define THR 1.0f

typedef unsigned int u32;
typedef unsigned long long u64;

// ---- weight fragments in device globals (filled by prep kernel) ----
__device__ u64 gW2f[3 * 16 * 8 * 32];   // [s][nb16][kc8][lane]
__device__ u64 gW3f[3 * 8 * 8 * 32];    // [s][nb8][kc8][lane]
__device__ u64 gW4f[3 * 2 * 4 * 32];    // [s][nb2][kc4][lane]

// ---- smem byte offsets ----
#define SS1 0        // 32 x 256B
#define SS2 8192     // 32 x 256B
#define SS3 16384    // 32 x 128B
#define SW1F 20480   // w1 fp32: 128 x 16 x 4B = 8192
#define SM_TOTAL 28672

__device__ __forceinline__ float bfv(float v) { return __bfloat162float(__float2bfloat16(v)); }
__device__ __forceinline__ u32 bfb(float v) { return (u32)__bfloat16_as_ushort(__float2bfloat16(v)); }

__device__ __forceinline__ float split_lvl(float v, int s) {
    float s0 = bfv(v);
    if (s == 0) return s0;
    float r = v - s0;
    float s1 = bfv(r);
    if (s == 1) return s1;
    return bfv(r - s1);
}

__global__ void prep_kernel(const float* __restrict__ w2g,
                            const float* __restrict__ w3g, const float* __restrict__ w4g)
{
    int idx = blockIdx.x * blockDim.x + threadIdx.x;
    int lane = idx & 31;
    int nrow = lane >> 2;
    int koff = (lane & 3) * 2;
    if (idx < 12288) {             // W2: [3][16][8][32]
        int f = idx >> 5; int kc = f & 7; int nb = (f >> 3) & 15; int s = f >> 7;
        int n = nb * 8 + nrow; int k = kc * 16 + koff;
        u32 lo = bfb(split_lvl(w2g[n * 128 + k], s))     | (bfb(split_lvl(w2g[n * 128 + k + 1], s)) << 16);
        u32 hi = bfb(split_lvl(w2g[n * 128 + k + 8], s)) | (bfb(split_lvl(w2g[n * 128 + k + 9], s)) << 16);
        gW2f[idx] = (u64)lo | ((u64)hi << 32);
    } else if (idx < 18432) {      // W3: [3][8][8][32]
        int j = idx - 12288; int f = j >> 5; int kc = f & 7; int nb = (f >> 3) & 7; int s = f >> 6;
        int n = nb * 8 + nrow; int k = kc * 16 + koff;
        u32 lo = bfb(split_lvl(w3g[n * 128 + k], s))     | (bfb(split_lvl(w3g[n * 128 + k + 1], s)) << 16);
        u32 hi = bfb(split_lvl(w3g[n * 128 + k + 8], s)) | (bfb(split_lvl(w3g[n * 128 + k + 9], s)) << 16);
        gW3f[j] = (u64)lo | ((u64)hi << 32);
    } else if (idx < 19200) {      // W4: [3][2][4][32]
        int j = idx - 18432; int f = j >> 5; int kc = f & 3; int nb = (f >> 2) & 1; int s = f >> 3;
        int n = nb * 8 + nrow; int k = kc * 16 + koff;
        float a0 = (n < 10) ? w4g[n * 64 + k]     : 0.f;
        float a1 = (n < 10) ? w4g[n * 64 + k + 1] : 0.f;
        float a2 = (n < 10) ? w4g[n * 64 + k + 8] : 0.f;
        float a3 = (n < 10) ? w4g[n * 64 + k + 9] : 0.f;
        u32 lo = bfb(split_lvl(a0, s)) | (bfb(split_lvl(a1, s)) << 16);
        u32 hi = bfb(split_lvl(a2, s)) | (bfb(split_lvl(a3, s)) << 16);
        gW4f[j] = (u64)lo | ((u64)hi << 32);
    }
}

__device__ __forceinline__ void ldsm4(u32 a[4], u32 addr) {
    asm volatile("ldmatrix.sync.aligned.m8n8.x4.shared.b16 {%0,%1,%2,%3}, [%4];"
        : "=r"(a[0]), "=r"(a[1]), "=r"(a[2]), "=r"(a[3]) : "r"(addr));
}
__device__ __forceinline__ void mma_bf16(float d[4], const u32 a[4], u32 b0, u32 b1) {
    asm volatile("mma.sync.aligned.m16n8k16.row.col.f32.bf16.bf16.f32 "
        "{%0,%1,%2,%3}, {%4,%5,%6,%7}, {%8,%9}, {%0,%1,%2,%3};"
        : "+f"(d[0]), "+f"(d[1]), "+f"(d[2]), "+f"(d[3])
        : "r"(a[0]), "r"(a[1]), "r"(a[2]), "r"(a[3]), "r"(b0), "r"(b1));
}
__device__ __forceinline__ void sts32(u32 addr, u32 v) {
    asm volatile("st.shared.b32 [%0], %1;" :: "r"(addr), "r"(v) : "memory");
}
__device__ __forceinline__ void sts128(u32 addr, u32 a, u32 b, u32 c, u32 d) {
    asm volatile("st.shared.v4.b32 [%0], {%1,%2,%3,%4};"
        :: "r"(addr), "r"(a), "r"(b), "r"(c), "r"(d) : "memory");
}

__device__ __forceinline__ void lif4(float* mem, const float* d, u32 &p0, u32 &p1) {
    float s[4];
#pragma unroll
    for (int e = 0; e < 4; e++) {
        float m = mem[e];
        float reset = (m > THR) ? 1.0f : 0.0f;
        m = fmaf(BETA, m, d[e]) - reset;
        mem[e] = m;
        s[e] = (m > THR) ? 1.0f : 0.0f;
    }
    p0 = (s[0] != 0.0f ? 0x3F80u : 0u) | (s[1] != 0.0f ? 0x3F800000u : 0u);
    p1 = (s[2] != 0.0f ? 0x3F80u : 0u) | (s[3] != 0.0f ? 0x3F800000u : 0u);
}

__global__ void __launch_bounds__(THREADS, 2)
snn_mma_kernel(const float* __restrict__ x,
               const float* __restrict__ w1g,
               float* __restrict__ out,
               int Btot)
{
    __shared__ __align__(16) char sm[SM_TOTAL];
    u32 smb;
    asm("{ .reg .u64 t; cvta.to.shared.u64 t, %1; cvt.u32.u64 %0, t; }"
        : "=r"(smb) : "l"(sm));

    const int tid  = threadIdx.x;
    const int w    = tid >> 5;     // 4 warps
    const int lane = tid & 31;
    const int b0   = blockIdx.x * 32;

    // ---- stage w1 fp32 into smem ----
    float* w1s = (float*)(sm + SW1F);
    for (int i = tid; i < 128 * 16; i += THREADS)
        w1s[i] = w1g[i];

    // ---- lane roles ----
    const int arow = ((lane >> 3) & 1) * 8 + (lane & 7);
    const int ac   = lane >> 4;
    const int r_   = lane >> 2;
    const int c_   = lane & 3;
    const u32 rx8  = (u32)(lane & 7) << 4;

    const int Mw  = w >> 1, nb4 = w & 1;   // L4 role

    const u64* pW2 = gW2f + lane;
    const u64* pW3 = gW3f + lane;
    const u64* pW4 = gW4f + lane;

    // ---- membranes ----
    float m1[32], m2[32], m3[16], m4[4];
#pragma unroll
    for (int i = 0; i < 32; i++) { m1[i] = 0.f; m2[i] = 0.f; }
#pragma unroll
    for (int i = 0; i < 16; i++) m3[i] = 0.f;
#pragma unroll
    for (int i = 0; i < 4; i++)  m4[i] = 0.f;

    // L1-FFMA role: lane = batch, warp owns neurons 32w..32w+31
    const float* w1w = w1s + (32 * w) * 16;

    // ---- L1 via FFMA: x(tt) from global, w1 fp32 broadcast from smem ----
    auto do_L1f = [&](int tt) {
        const float* xg = x + ((size_t)tt * (size_t)Btot + (size_t)(b0 + lane)) * 16;
        float4 x0 = ((const float4*)xg)[0];
        float4 x1 = ((const float4*)xg)[1];
        float4 x2 = ((const float4*)xg)[2];
        float4 x3 = ((const float4*)xg)[3];
#pragma unroll
        for (int g = 0; g < 4; g++) {
            u32 pk[4];
#pragma unroll
            for (int i = 0; i < 8; i++) {
                int n = 8 * g + i;
                const float4* wr = (const float4*)(w1w + n * 16);
                float4 wa = wr[0], wb = wr[1], wc = wr[2], wd = wr[3];
                float cur = 0.f;
                cur = fmaf(x0.x, wa.x, cur); cur = fmaf(x0.y, wa.y, cur);
                cur = fmaf(x0.z, wa.z, cur); cur = fmaf(x0.w, wa.w, cur);
                cur = fmaf(x1.x, wb.x, cur); cur = fmaf(x1.y, wb.y, cur);
                cur = fmaf(x1.z, wb.z, cur); cur = fmaf(x1.w, wb.w, cur);
                cur = fmaf(x2.x, wc.x, cur); cur = fmaf(x2.y, wc.y, cur);
                cur = fmaf(x2.z, wc.z, cur); cur = fmaf(x2.w, wc.w, cur);
                cur = fmaf(x3.x, wd.x, cur); cur = fmaf(x3.y, wd.y, cur);
                cur = fmaf(x3.z, wd.z, cur); cur = fmaf(x3.w, wd.w, cur);
                float m = m1[n];
                float reset = (m > THR) ? 1.0f : 0.0f;
                m = fmaf(BETA, m, cur) - reset;
                m1[n] = m;
                u32 h = (m > THR) ? 0x3F80u : 0u;
                if ((i & 1) == 0) pk[i >> 1] = h;
                else              pk[i >> 1] |= (h << 16);
            }
            u32 a0 = smb + SS1 + (u32)(lane * 256)
                     + (((u32)(4 * w + g) << 4) ^ ((u32)(lane & 7) << 4));
            sts128(a0, pk[0], pk[1], pk[2], pk[3]);
        }
    };

    auto do_L4 = [&](int tt) {   // warp (Mw, nb4): M16 x N8, K=64
        float acc[4] = {0.f, 0.f, 0.f, 0.f};
#pragma unroll
        for (int kc = 0; kc < 4; kc++) {
            u32 a_[4];
            ldsm4(a_, smb + SS3 + (u32)((16 * Mw + arow) * 128)
                      + (((u32)(2 * kc + ac) << 4) ^ rx8));
#pragma unroll
            for (int s = 0; s < 3; s++) {
                u64 q = pW4[((s * 2 + nb4) * 4 + kc) * 32];
                mma_bf16(acc, a_, (u32)q, (u32)(q >> 32));
            }
        }
        float s4[4];
#pragma unroll
        for (int e = 0; e < 4; e++) {
            float m = m4[e];
            float reset = (m > THR) ? 1.0f : 0.0f;
            m = fmaf(BETA, m, acc[e]) - reset;
            m4[e] = m;
            s4[e] = (m > THR) ? 1.0f : 0.0f;
        }
        size_t row0 = (size_t)tt * (size_t)Btot + (size_t)(b0 + 16 * Mw + r_);
        if (nb4 == 0) {
            *(float2*)(out + row0 * 10 + 2 * c_)       = make_float2(s4[0], s4[1]);
            *(float2*)(out + (row0 + 8) * 10 + 2 * c_) = make_float2(s4[2], s4[3]);
        } else if (c_ == 0) {
            *(float2*)(out + row0 * 10 + 8)       = make_float2(s4[0], s4[1]);
            *(float2*)(out + (row0 + 8) * 10 + 8) = make_float2(s4[2], s4[3]);
        }
    };

    // ===== prologue: w1 visible; L1(0) =====
    __syncthreads();
    do_L1f(0);
    __syncthreads();

    for (int t = 0; t < T_STEPS; t++) {
        // ===== phase A: L4(t-1) + L2(t) =====
        {
            if (t > 0)
                do_L4(t - 1);

            // L2: warp M32 x N32, K=128, 3 splits
            float acc[32];
#pragma unroll
            for (int i = 0; i < 32; i++) acc[i] = 0.f;
#pragma unroll
            for (int kc = 0; kc < 8; kc++) {
                u32 a_[2][4];
#pragma unroll
                for (int M = 0; M < 2; M++)
                    ldsm4(a_[M], smb + SS1 + (u32)((16 * M + arow) * 256)
                                 + (((u32)(2 * kc + ac) << 4) ^ rx8));
#pragma unroll
                for (int s = 0; s < 3; s++) {
                    u64 q[4];
#pragma unroll
                    for (int j = 0; j < 4; j++)
                        q[j] = pW2[((s * 16 + (w * 4 + j)) * 8 + kc) * 32];
#pragma unroll
                    for (int M = 0; M < 2; M++)
#pragma unroll
                        for (int j = 0; j < 4; j++)
                            mma_bf16(&acc[(M * 4 + j) * 4], a_[M], (u32)q[j], (u32)(q[j] >> 32));
                }
            }
#pragma unroll
            for (int M = 0; M < 2; M++)
#pragma unroll
                for (int j = 0; j < 4; j++) {
                    u32 p0, p1;
                    lif4(&m2[(M * 4 + j) * 4], &acc[(M * 4 + j) * 4], p0, p1);
                    u32 a0 = smb + SS2 + (u32)((16 * M + r_) * 256)
                             + (((u32)(4 * w + j) << 4) ^ ((u32)r_ << 4)) + 4 * c_;
                    sts32(a0, p0);
                    sts32(a0 + 2048, p1);
                }
        }
        __syncthreads();

        // ===== phase B: L3(t) + L1(t+1) via FFMA =====
        {
            // L3: warp M32 x N16 (n16 block = w), K=128, 3 splits
            float acc[16];
#pragma unroll
            for (int i = 0; i < 16; i++) acc[i] = 0.f;
#pragma unroll
            for (int kc = 0; kc < 8; kc++) {
                u32 a_[2][4];
#pragma unroll
                for (int M = 0; M < 2; M++)
                    ldsm4(a_[M], smb + SS2 + (u32)((16 * M + arow) * 256)
                                 + (((u32)(2 * kc + ac) << 4) ^ rx8));
#pragma unroll
                for (int s = 0; s < 3; s++) {
                    u64 q0 = pW3[((s * 8 + (w * 2 + 0)) * 8 + kc) * 32];
                    u64 q1 = pW3[((s * 8 + (w * 2 + 1)) * 8 + kc) * 32];
#pragma unroll
                    for (int M = 0; M < 2; M++) {
                        mma_bf16(&acc[(M * 2 + 0) * 4], a_[M], (u32)q0, (u32)(q0 >> 32));
                        mma_bf16(&acc[(M * 2 + 1) * 4], a_[M], (u32)q1, (u32)(q1 >> 32));
                    }
                }
            }
#pragma unroll
            for (int M = 0; M < 2; M++)
#pragma unroll
                for (int nb = 0; nb < 2; nb++) {
                    u32 p0, p1;
                    lif4(&m3[(M * 2 + nb) * 4], &acc[(M * 2 + nb) * 4], p0, p1);
                    u32 a0 = smb + SS3 + (u32)((16 * M + r_) * 128)
                             + (((u32)(2 * w + nb) << 4) ^ ((u32)r_ << 4)) + 4 * c_;
                    sts32(a0, p0);
                    sts32(a0 + 1024, p1);
                }

            if (t + 1 < T_STEPS)
                do_L1f(t + 1);
        }
        __syncthreads();
    }

    // ===== epilogue: L4(T-1) =====
    do_L4(T_STEPS - 1);
}

extern "C" void kernel_launch(void* const* d_in, const int* in_sizes, int n_in,
                              void* d_out, int out_size) {
    const float* x  = (const float*)d_in[0];
    const float* w1 = (const float*)d_in[1];
    const float* w2 = (const float*)d_in[2];
    const float* w3 = (const float*)d_in[3];
    const float* w4 = (const float*)d_in[4];
    float* out = (float*)d_out;

    const int Btot = in_sizes[0] / (T_STEPS * 16);  // 65536

    prep_kernel<<<(19200 + 127) / 128, 128>>>(w2, w3, w4);

    const int grid = Btot / 32;                     // 2048
    snn_mma_kernel<<<grid, THREADS>>>(x, w1, out, Btot);
}

// round 17
// speedup vs baseline: 1.2124x; 1.1261x over previous
#include <cuda_runtime.h>
#include <cuda_bf16.h>

#define THREADS 128
#define T_STEPS 20
#define BETA 0.9f
#define THR 1.0f

typedef unsigned int u32;
typedef unsigned long long u64;

// ---- weight fragments in device globals (filled by prep kernel) ----
__device__ u64 gW2f[3 * 16 * 8 * 32];   // [s][nb16][kc8][lane]
__device__ u64 gW3f[3 * 8 * 8 * 32];    // [s][nb8][kc8][lane]
__device__ u64 gW1f[3 * 16 * 32];       // [s][nb16][lane]
__device__ u64 gW4f[3 * 2 * 4 * 32];    // [s][nb2][kc4][lane]

// ---- smem byte offsets (spike/x buffers only) ----
#define SS1 0        // 32 x 256B
#define SS2 8192     // 32 x 256B
#define SS3 16384    // 32 x 128B
#define SXS 20480    // 3 x 32 x 32B
#define SM_TOTAL 23552

__device__ __forceinline__ float bfv(float v) { return __bfloat162float(__float2bfloat16(v)); }
__device__ __forceinline__ u32 bfb(float v) { return (u32)__bfloat16_as_ushort(__float2bfloat16(v)); }

__device__ __forceinline__ float split_lvl(float v, int s) {
    float s0 = bfv(v);
    if (s == 0) return s0;
    float r = v - s0;
    float s1 = bfv(r);
    if (s == 1) return s1;
    return bfv(r - s1);
}

__global__ void prep_kernel(const float* __restrict__ w1g, const float* __restrict__ w2g,
                            const float* __restrict__ w3g, const float* __restrict__ w4g)
{
    int idx = blockIdx.x * blockDim.x + threadIdx.x;
    int lane = idx & 31;
    int nrow = lane >> 2;
    int koff = (lane & 3) * 2;
    if (idx < 12288) {             // W2: [3][16][8][32]
        int f = idx >> 5; int kc = f & 7; int nb = (f >> 3) & 15; int s = f >> 7;
        int n = nb * 8 + nrow; int k = kc * 16 + koff;
        u32 lo = bfb(split_lvl(w2g[n * 128 + k], s))     | (bfb(split_lvl(w2g[n * 128 + k + 1], s)) << 16);
        u32 hi = bfb(split_lvl(w2g[n * 128 + k + 8], s)) | (bfb(split_lvl(w2g[n * 128 + k + 9], s)) << 16);
        gW2f[idx] = (u64)lo | ((u64)hi << 32);
    } else if (idx < 18432) {      // W3: [3][8][8][32]
        int j = idx - 12288; int f = j >> 5; int kc = f & 7; int nb = (f >> 3) & 7; int s = f >> 6;
        int n = nb * 8 + nrow; int k = kc * 16 + koff;
        u32 lo = bfb(split_lvl(w3g[n * 128 + k], s))     | (bfb(split_lvl(w3g[n * 128 + k + 1], s)) << 16);
        u32 hi = bfb(split_lvl(w3g[n * 128 + k + 8], s)) | (bfb(split_lvl(w3g[n * 128 + k + 9], s)) << 16);
        gW3f[j] = (u64)lo | ((u64)hi << 32);
    } else if (idx < 19968) {      // W1: [3][16][32]
        int j = idx - 18432; int f = j >> 5; int nb = f & 15; int s = f >> 4;
        int n = nb * 8 + nrow; int k = koff;
        u32 lo = bfb(split_lvl(w1g[n * 16 + k], s))     | (bfb(split_lvl(w1g[n * 16 + k + 1], s)) << 16);
        u32 hi = bfb(split_lvl(w1g[n * 16 + k + 8], s)) | (bfb(split_lvl(w1g[n * 16 + k + 9], s)) << 16);
        gW1f[j] = (u64)lo | ((u64)hi << 32);
    } else if (idx < 20736) {      // W4: [3][2][4][32]
        int j = idx - 19968; int f = j >> 5; int kc = f & 3; int nb = (f >> 2) & 1; int s = f >> 3;
        int n = nb * 8 + nrow; int k = kc * 16 + koff;
        float a0 = (n < 10) ? w4g[n * 64 + k]     : 0.f;
        float a1 = (n < 10) ? w4g[n * 64 + k + 1] : 0.f;
        float a2 = (n < 10) ? w4g[n * 64 + k + 8] : 0.f;
        float a3 = (n < 10) ? w4g[n * 64 + k + 9] : 0.f;
        u32 lo = bfb(split_lvl(a0, s)) | (bfb(split_lvl(a1, s)) << 16);
        u32 hi = bfb(split_lvl(a2, s)) | (bfb(split_lvl(a3, s)) << 16);
        gW4f[j] = (u64)lo | ((u64)hi << 32);
    }
}

__device__ __forceinline__ void ldsm4(u32 a[4], u32 addr) {
    asm volatile("ldmatrix.sync.aligned.m8n8.x4.shared.b16 {%0,%1,%2,%3}, [%4];"
        : "=r"(a[0]), "=r"(a[1]), "=r"(a[2]), "=r"(a[3]) : "r"(addr));
}
__device__ __forceinline__ void mma_bf16(float d[4], const u32 a[4], u32 b0, u32 b1) {
    asm volatile("mma.sync.aligned.m16n8k16.row.col.f32.bf16.bf16.f32 "
        "{%0,%1,%2,%3}, {%4,%5,%6,%7}, {%8,%9}, {%0,%1,%2,%3};"
        : "+f"(d[0]), "+f"(d[1]), "+f"(d[2]), "+f"(d[3])
        : "r"(a[0]), "r"(a[1]), "r"(a[2]), "r"(a[3]), "r"(b0), "r"(b1));
}
__device__ __forceinline__ void sts32(u32 addr, u32 v) {
    asm volatile("st.shared.b32 [%0], %1;" :: "r"(addr), "r"(v) : "memory");
}

__device__ __forceinline__ void lif4(float* mem, const float* d, u32 &p0, u32 &p1) {
    float s[4];
#pragma unroll
    for (int e = 0; e < 4; e++) {
        float m = mem[e];
        float reset = (m > THR) ? 1.0f : 0.0f;
        m = fmaf(BETA, m, d[e]) - reset;
        mem[e] = m;
        s[e] = (m > THR) ? 1.0f : 0.0f;
    }
    p0 = (s[0] != 0.0f ? 0x3F80u : 0u) | (s[1] != 0.0f ? 0x3F800000u : 0u);
    p1 = (s[2] != 0.0f ? 0x3F80u : 0u) | (s[3] != 0.0f ? 0x3F800000u : 0u);
}

__global__ void __launch_bounds__(THREADS, 2)
snn_mma_kernel(const float* __restrict__ x,
               float* __restrict__ out,
               int Btot)
{
    __shared__ __align__(16) char sm[SM_TOTAL];
    u32 smb;
    asm("{ .reg .u64 t; cvta.to.shared.u64 t, %1; cvt.u32.u64 %0, t; }"
        : "=r"(smb) : "l"(sm));

    const int tid  = threadIdx.x;
    const int w    = tid >> 5;     // 4 warps
    const int lane = tid & 31;
    const int b0   = blockIdx.x * 32;

    // ---- phase skew: offset odd wave-slot blocks by ~2600 cyc so the two
    // co-resident blocks on an SM interleave HMMA and non-HMMA stretches ----
    if (((blockIdx.x / 148) & 1) == 1) {
        float a = (float)(tid + 1);
#pragma unroll 1
        for (int i = 0; i < 650; i++)
            asm volatile("fma.rn.f32 %0, %0, 0f3F800001, 0f33000000;" : "+f"(a));
        if (a < 0.0f)  // never true (a stays positive); defeats DCE
            out[0] = a;
    }

    // ---- lane roles ----
    const int arow = ((lane >> 3) & 1) * 8 + (lane & 7);
    const int ac   = lane >> 4;
    const int r_   = lane >> 2;
    const int c_   = lane & 3;
    const u32 rx8  = (u32)(lane & 7) << 4;

    const int Mw  = w >> 1, nb4 = w & 1;   // L4 role

    const u64* pW2 = gW2f + lane;
    const u64* pW3 = gW3f + lane;
    const u64* pW4 = gW4f + lane;

    // ---- hoist L1 B fragments (constant over t): 3 lv x 4 n8 ----
    u32 bw1[3][4][2];
#pragma unroll
    for (int lv = 0; lv < 3; lv++)
#pragma unroll
        for (int j = 0; j < 4; j++) {
            u64 q = gW1f[(lv * 16 + (w * 4 + j)) * 32 + lane];
            bw1[lv][j][0] = (u32)q;
            bw1[lv][j][1] = (u32)(q >> 32);
        }

    // ---- membranes ----
    float m1[32], m2[32], m3[16], m4[4];
#pragma unroll
    for (int i = 0; i < 32; i++) { m1[i] = 0.f; m2[i] = 0.f; }
#pragma unroll
    for (int i = 0; i < 16; i++) m3[i] = 0.f;
#pragma unroll
    for (int i = 0; i < 4; i++)  m4[i] = 0.f;

    // ---- x staging role: thread owns (batch bsx, feats f4..f4+3) ----
    const int bsx = tid >> 2;
    const int f4  = (tid & 3) << 2;
    const u32 xbase = smb + SXS + (u32)(bsx * 32 + (((f4 >> 3) ^ (bsx & 1)) << 4) + (f4 & 7) * 2);

    auto stage_x = [&](const float4& v) {
        float e0 = v.x - bfv(v.x), e1 = v.y - bfv(v.y), e2 = v.z - bfv(v.z), e3 = v.w - bfv(v.w);
        float g0 = e0 - bfv(e0), g1 = e1 - bfv(e1), g2 = e2 - bfv(e2), g3 = e3 - bfv(e3);
        sts32(xbase,            bfb(v.x) | (bfb(v.y) << 16));
        sts32(xbase + 4,        bfb(v.z) | (bfb(v.w) << 16));
        sts32(xbase + 1024,     bfb(e0) | (bfb(e1) << 16));
        sts32(xbase + 1024 + 4, bfb(e2) | (bfb(e3) << 16));
        sts32(xbase + 2048,     bfb(g0) | (bfb(g1) << 16));
        sts32(xbase + 2048 + 4, bfb(g2) | (bfb(g3) << 16));
    };

    auto do_L1 = [&]() {   // warp M32 x N32, K=16, 6 split terms -> s1
        float acc[32];
#pragma unroll
        for (int i = 0; i < 32; i++) acc[i] = 0.f;
        const int la[6] = {0, 0, 1, 0, 1, 2};
        const int lb[6] = {0, 1, 0, 2, 1, 0};
#pragma unroll
        for (int M = 0; M < 2; M++) {
            u32 ax[3][4];
#pragma unroll
            for (int lv = 0; lv < 3; lv++)
                ldsm4(ax[lv], smb + SXS + (u32)(lv * 1024 + (16 * M + arow) * 32)
                              + (((u32)ac << 4) ^ ((u32)(arow & 1) << 4)));
#pragma unroll
            for (int s = 0; s < 6; s++)
#pragma unroll
                for (int j = 0; j < 4; j++)
                    mma_bf16(&acc[(M * 4 + j) * 4], ax[la[s]], bw1[lb[s]][j][0], bw1[lb[s]][j][1]);
        }
#pragma unroll
        for (int M = 0; M < 2; M++)
#pragma unroll
            for (int j = 0; j < 4; j++) {
                u32 p0, p1;
                lif4(&m1[(M * 4 + j) * 4], &acc[(M * 4 + j) * 4], p0, p1);
                u32 a0 = smb + SS1 + (u32)((16 * M + r_) * 256)
                         + (((u32)(4 * w + j) << 4) ^ ((u32)r_ << 4)) + 4 * c_;
                sts32(a0, p0);
                sts32(a0 + 2048, p1);
            }
    };

    auto do_L4 = [&](int tt) {   // warp (Mw, nb4): M16 x N8, K=64
        float acc[4] = {0.f, 0.f, 0.f, 0.f};
#pragma unroll
        for (int kc = 0; kc < 4; kc++) {
            u32 a_[4];
            ldsm4(a_, smb + SS3 + (u32)((16 * Mw + arow) * 128)
                      + (((u32)(2 * kc + ac) << 4) ^ rx8));
#pragma unroll
            for (int s = 0; s < 3; s++) {
                u64 q = pW4[((s * 2 + nb4) * 4 + kc) * 32];
                mma_bf16(acc, a_, (u32)q, (u32)(q >> 32));
            }
        }
        float s4[4];
#pragma unroll
        for (int e = 0; e < 4; e++) {
            float m = m4[e];
            float reset = (m > THR) ? 1.0f : 0.0f;
            m = fmaf(BETA, m, acc[e]) - reset;
            m4[e] = m;
            s4[e] = (m > THR) ? 1.0f : 0.0f;
        }
        size_t row0 = (size_t)tt * (size_t)Btot + (size_t)(b0 + 16 * Mw + r_);
        if (nb4 == 0) {
            *(float2*)(out + row0 * 10 + 2 * c_)       = make_float2(s4[0], s4[1]);
            *(float2*)(out + (row0 + 8) * 10 + 2 * c_) = make_float2(s4[2], s4[3]);
        } else if (c_ == 0) {
            *(float2*)(out + row0 * 10 + 8)       = make_float2(s4[0], s4[1]);
            *(float2*)(out + (row0 + 8) * 10 + 8) = make_float2(s4[2], s4[3]);
        }
    };

    // ===== prologue: stage x(0); L1(0) =====
    {
        float4 v = *(const float4*)(x + ((size_t)0 * (size_t)Btot + (size_t)(b0 + bsx)) * 16 + f4);
        stage_x(v);
    }
    __syncthreads();
    do_L1();
    __syncthreads();

    for (int t = 0; t < T_STEPS; t++) {
        // ===== phase A: L4(t-1) + L2(t) + stage x(t+1) =====
        {
            float4 xv;
            if (t + 1 < T_STEPS)
                xv = *(const float4*)(x + ((size_t)(t + 1) * (size_t)Btot + (size_t)(b0 + bsx)) * 16 + f4);

            if (t > 0)
                do_L4(t - 1);

            float acc[32];
#pragma unroll
            for (int i = 0; i < 32; i++) acc[i] = 0.f;
#pragma unroll
            for (int kc = 0; kc < 8; kc++) {
                u32 a_[2][4];
#pragma unroll
                for (int M = 0; M < 2; M++)
                    ldsm4(a_[M], smb + SS1 + (u32)((16 * M + arow) * 256)
                                 + (((u32)(2 * kc + ac) << 4) ^ rx8));
#pragma unroll
                for (int s = 0; s < 3; s++) {
                    u64 q[4];
#pragma unroll
                    for (int j = 0; j < 4; j++)
                        q[j] = pW2[((s * 16 + (w * 4 + j)) * 8 + kc) * 32];
#pragma unroll
                    for (int M = 0; M < 2; M++)
#pragma unroll
                        for (int j = 0; j < 4; j++)
                            mma_bf16(&acc[(M * 4 + j) * 4], a_[M], (u32)q[j], (u32)(q[j] >> 32));
                }
            }
#pragma unroll
            for (int M = 0; M < 2; M++)
#pragma unroll
                for (int j = 0; j < 4; j++) {
                    u32 p0, p1;
                    lif4(&m2[(M * 4 + j) * 4], &acc[(M * 4 + j) * 4], p0, p1);
                    u32 a0 = smb + SS2 + (u32)((16 * M + r_) * 256)
                             + (((u32)(4 * w + j) << 4) ^ ((u32)r_ << 4)) + 4 * c_;
                    sts32(a0, p0);
                    sts32(a0 + 2048, p1);
                }

            if (t + 1 < T_STEPS)
                stage_x(xv);
        }
        __syncthreads();

        // ===== phase B: L3(t) + L1(t+1) =====
        {
            float acc[16];
#pragma unroll
            for (int i = 0; i < 16; i++) acc[i] = 0.f;
#pragma unroll
            for (int kc = 0; kc < 8; kc++) {
                u32 a_[2][4];
#pragma unroll
                for (int M = 0; M < 2; M++)
                    ldsm4(a_[M], smb + SS2 + (u32)((16 * M + arow) * 256)
                                 + (((u32)(2 * kc + ac) << 4) ^ rx8));
#pragma unroll
                for (int s = 0; s < 3; s++) {
                    u64 q0 = pW3[((s * 8 + (w * 2 + 0)) * 8 + kc) * 32];
                    u64 q1 = pW3[((s * 8 + (w * 2 + 1)) * 8 + kc) * 32];
#pragma unroll
                    for (int M = 0; M < 2; M++) {
                        mma_bf16(&acc[(M * 2 + 0) * 4], a_[M], (u32)q0, (u32)(q0 >> 32));
                        mma_bf16(&acc[(M * 2 + 1) * 4], a_[M], (u32)q1, (u32)(q1 >> 32));
                    }
                }
            }
#pragma unroll
            for (int M = 0; M < 2; M++)
#pragma unroll
                for (int nb = 0; nb < 2; nb++) {
                    u32 p0, p1;
                    lif4(&m3[(M * 2 + nb) * 4], &acc[(M * 2 + nb) * 4], p0, p1);
                    u32 a0 = smb + SS3 + (u32)((16 * M + r_) * 128)
                             + (((u32)(2 * w + nb) << 4) ^ ((u32)r_ << 4)) + 4 * c_;
                    sts32(a0, p0);
                    sts32(a0 + 1024, p1);
                }

            if (t + 1 < T_STEPS)
                do_L1();
        }
        __syncthreads();
    }

    // ===== epilogue: L4(T-1) =====
    do_L4(T_STEPS - 1);
}

extern "C" void kernel_launch(void* const* d_in, const int* in_sizes, int n_in,
                              void* d_out, int out_size) {
    const float* x  = (const float*)d_in[0];
    const float* w1 = (const float*)d_in[1];
    const float* w2 = (const float*)d_in[2];
    const float* w3 = (const float*)d_in[3];
    const float* w4 = (const float*)d_in[4];
    float* out = (float*)d_out;

    const int Btot = in_sizes[0] / (T_STEPS * 16);  // 65536

    prep_kernel<<<(20736 + 127) / 128, 128>>>(w1, w2, w3, w4);

    const int grid = Btot / 32;                     // 2048
    snn_mma_kernel<<<grid, THREADS>>>(x, out, Btot);
}